// round 4
// baseline (speedup 1.0000x reference)
#include <cuda_runtime.h>

// Problem constants
#define BQ 4          // batch
#define NP 16384      // points
#define NQ 4096       // queries (npoint)
#define CF 64         // feature channels
#define KS 32         // nsample
#define OUTC (CF + 3) // 67 output channels

#define WPB 8         // warps (queries) per block
#define TILE 1024     // shared-memory tile of points
#define CAP 160       // per-warp candidate buffer (max 31 carry + 128 new)

#define FULLM 0xffffffffu
// +inf distance, max index: any real key sorts below this.
#define INFKEY 0x7f800000ffffffffULL

// Scratch: final neighbor indices (2 MB) + transposed features (16 MB).
__device__ int   g_idx[(size_t)BQ * NQ * KS];
__device__ float g_ft[(size_t)BQ * NP * CF];   // (B, N, C)

__device__ __forceinline__ unsigned long long pack_key(float d, int idx) {
    // d >= 0 -> float bits are order-preserving; (dist, idx) lexicographic.
    return ((unsigned long long)__float_as_uint(d) << 32) | (unsigned int)idx;
}

// Warp-wide bitonic sort, ascending, one key per lane.
__device__ __forceinline__ unsigned long long
warp_bitonic_sort(unsigned long long key, int lane) {
#pragma unroll
    for (int k = 2; k <= 32; k <<= 1) {
#pragma unroll
        for (int j = k >> 1; j > 0; j >>= 1) {
            unsigned long long other = __shfl_xor_sync(FULLM, key, j);
            bool take_min = (((lane & k) == 0) == ((lane & j) == 0));
            bool lt = key < other;
            key = (take_min == lt) ? key : other;
        }
    }
    return key;
}

// Keep lowest 32 of (top asc-sorted) U (cand asc-sorted), result asc-sorted.
__device__ __forceinline__ unsigned long long
warp_merge_topk(unsigned long long top, unsigned long long cand, int lane) {
    unsigned long long crev = __shfl_sync(FULLM, cand, 31 - lane);
    unsigned long long v = (top < crev) ? top : crev;   // bitonic, = lowest 32
#pragma unroll
    for (int j = 16; j > 0; j >>= 1) {                  // bitonic cleanup
        unsigned long long other = __shfl_xor_sync(FULLM, v, j);
        bool lower = (lane & j) == 0;
        bool lt = v < other;
        v = (lower == lt) ? v : other;
    }
    return v;
}

// ---------------------------------------------------------------------------
// Kernel 1: exact KNN, one WARP per query.
// Hot loop: 4 points/lane, float-only threshold test, single vote gate.
// Exactness of the float filter: any future candidate has a larger index
// than the current rank-32 entry (ascending scan), so equal distances lose
// the (dist, idx) tiebreak anyway -> strict 'd < thresh' misses nothing.
// ---------------------------------------------------------------------------
__global__ __launch_bounds__(WPB * 32)
void knn_kernel(const float* __restrict__ xyz,
                const float* __restrict__ new_xyz) {
    const int b    = blockIdx.y;
    const int warp = threadIdx.x >> 5;
    const int lane = threadIdx.x & 31;
    const int q    = blockIdx.x * WPB + warp;
    const unsigned ltmask = (1u << lane) - 1u;

    const float* qp = new_xyz + ((size_t)b * NQ + q) * 3;
    const float qx = qp[0], qy = qp[1], qz = qp[2];

    __shared__ float s_x[TILE], s_y[TILE], s_z[TILE];     // 12 KB
    __shared__ unsigned long long s_cand[WPB][CAP];       // 10 KB

    unsigned long long top = INFKEY;
    float thf = __int_as_float(0x7f800000);   // +inf
    int cnt = 0;

    for (int t0 = 0; t0 < NP; t0 += TILE) {
        __syncthreads();
        {
            const float* src = xyz + ((size_t)b * NP + t0) * 3;
            for (int i = threadIdx.x; i < TILE * 3; i += WPB * 32) {
                const float v = src[i];
                const int pt = i / 3;
                const int r  = i - pt * 3;
                if (r == 0)      s_x[pt] = v;
                else if (r == 1) s_y[pt] = v;
                else             s_z[pt] = v;
            }
        }
        __syncthreads();

        for (int j = 0; j < TILE; j += 128) {
            float d0, d1, d2, d3;
            {
                const int j0 = j + lane;
                float dx = qx - s_x[j0],      dy = qy - s_y[j0],      dz = qz - s_z[j0];
                d0 = fmaf(dx, dx, fmaf(dy, dy, dz * dz));
                dx = qx - s_x[j0 + 32];  dy = qy - s_y[j0 + 32];  dz = qz - s_z[j0 + 32];
                d1 = fmaf(dx, dx, fmaf(dy, dy, dz * dz));
                dx = qx - s_x[j0 + 64];  dy = qy - s_y[j0 + 64];  dz = qz - s_z[j0 + 64];
                d2 = fmaf(dx, dx, fmaf(dy, dy, dz * dz));
                dx = qx - s_x[j0 + 96];  dy = qy - s_y[j0 + 96];  dz = qz - s_z[j0 + 96];
                d3 = fmaf(dx, dx, fmaf(dy, dy, dz * dz));
            }
            const bool p0 = d0 < thf, p1 = d1 < thf, p2 = d2 < thf, p3 = d3 < thf;
            if (__any_sync(FULLM, p0 | p1 | p2 | p3)) {
                unsigned m;
                m = __ballot_sync(FULLM, p0);
                if (p0) s_cand[warp][cnt + __popc(m & ltmask)] =
                            pack_key(d0, t0 + j + lane);
                cnt += __popc(m);
                m = __ballot_sync(FULLM, p1);
                if (p1) s_cand[warp][cnt + __popc(m & ltmask)] =
                            pack_key(d1, t0 + j + 32 + lane);
                cnt += __popc(m);
                m = __ballot_sync(FULLM, p2);
                if (p2) s_cand[warp][cnt + __popc(m & ltmask)] =
                            pack_key(d2, t0 + j + 64 + lane);
                cnt += __popc(m);
                m = __ballot_sync(FULLM, p3);
                if (p3) s_cand[warp][cnt + __popc(m & ltmask)] =
                            pack_key(d3, t0 + j + 96 + lane);
                cnt += __popc(m);

                while (cnt >= 32) {   // fold last 32 (order irrelevant: sorted)
                    unsigned long long c = s_cand[warp][cnt - 32 + lane];
                    c   = warp_bitonic_sort(c, lane);
                    top = warp_merge_topk(top, c, lane);
                    cnt -= 32;
                    thf = __uint_as_float(
                        (unsigned)(__shfl_sync(FULLM, top, 31) >> 32));
                }
            }
        }
    }
    if (cnt > 0) {
        unsigned long long c = (lane < cnt) ? s_cand[warp][lane] : INFKEY;
        c   = warp_bitonic_sort(c, lane);
        top = warp_merge_topk(top, c, lane);
    }

    // top is ascending by (dist, idx) -> slot order matches top_k output.
    g_idx[((size_t)b * NQ + q) * KS + lane] = (int)(top & 0xffffffffu);
}

// ---------------------------------------------------------------------------
// Kernel 0: feature transpose (B, C, N) -> (B, N, C).
// ---------------------------------------------------------------------------
__global__ __launch_bounds__(256)
void transpose_kernel(const float* __restrict__ feat) {
    __shared__ float t[32][33];
    const int b  = blockIdx.z;
    const int n0 = blockIdx.x * 32;
    const int c0 = blockIdx.y * 32;
    const int tx = threadIdx.x;
    const int ty = threadIdx.y;
#pragma unroll
    for (int i = 0; i < 4; i++) {
        const int c = c0 + ty + i * 8;
        t[ty + i * 8][tx] = feat[((size_t)b * CF + c) * NP + n0 + tx];
    }
    __syncthreads();
#pragma unroll
    for (int i = 0; i < 4; i++) {
        const int n = n0 + ty + i * 8;
        g_ft[((size_t)b * NP + n) * CF + c0 + tx] = t[tx][ty + i * 8];
    }
}

// ---------------------------------------------------------------------------
// Kernel 2: gather / center / transpose / concat. One query per block.
// ---------------------------------------------------------------------------
__global__ __launch_bounds__(128)
void group_kernel(const float* __restrict__ xyz,
                  const float* __restrict__ new_xyz,
                  float* __restrict__ out) {
    const int p   = blockIdx.x;
    const int b   = blockIdx.y;
    const int tid = threadIdx.x;
    const int w    = tid >> 5;
    const int lane = tid & 31;

    __shared__ int   sidx[KS];
    __shared__ float sfeat[KS][65];

    if (tid < KS) sidx[tid] = g_idx[((size_t)b * NQ + p) * KS + tid];
    __syncthreads();

    // Stage neighbor feature rows: warp w loads rows w, w+4, ... (256B each).
    for (int s = w; s < KS; s += 4) {
        const float2* row =
            (const float2*)(g_ft + ((size_t)b * NP + sidx[s]) * CF);
        const float2 v = row[lane];
        sfeat[s][lane * 2]     = v.x;
        sfeat[s][lane * 2 + 1] = v.y;
    }
    __syncthreads();

    const int i = sidx[lane];
    for (int c = w; c < OUTC; c += 4) {
        float v;
        if (c < 3) {
            v = xyz[((size_t)b * NP + i) * 3 + c] -
                new_xyz[((size_t)b * NQ + p) * 3 + c];
        } else {
            v = sfeat[lane][c - 3];
        }
        out[(((size_t)b * OUTC + c) * NQ + p) * KS + lane] = v;
    }
}

extern "C" void kernel_launch(void* const* d_in, const int* in_sizes, int n_in,
                              void* d_out, int out_size) {
    const float* xyz     = (const float*)d_in[0];  // (B, N, 3)
    const float* new_xyz = (const float*)d_in[1];  // (B, NPOINT, 3)
    const float* feat    = (const float*)d_in[2];  // (B, C, N)
    float* out = (float*)d_out;                    // (B, 67, NPOINT, 32)

    // knn first so ncu's (-s 5 -c 1) capture lands on it.
    dim3 g1(NQ / WPB, BQ);
    knn_kernel<<<g1, WPB * 32>>>(xyz, new_xyz);

    dim3 gt(NP / 32, CF / 32, BQ);
    transpose_kernel<<<gt, dim3(32, 8)>>>(feat);

    dim3 g2(NQ, BQ);
    group_kernel<<<g2, 128>>>(xyz, new_xyz, out);
}

// round 5
// speedup vs baseline: 1.5510x; 1.5510x over previous
#include <cuda_runtime.h>

// Problem constants
#define BQ 4          // batch
#define NP 16384      // points
#define NQ 4096       // queries (npoint)
#define CF 64         // feature channels
#define KS 32         // nsample
#define OUTC (CF + 3) // 67 output channels

#define WPB 8         // warps (queries) per block
#define TILE 2048     // shared-memory tile of points
#define CAP 160       // per-warp candidate buffer (max 31 carry + 128 new)

#define FULLM 0xffffffffu
// +inf distance, max index: any real key sorts below this.
#define INFKEY 0x7f800000ffffffffULL

// Scratch: final neighbor indices (2 MB) + transposed features (16 MB).
__device__ int   g_idx[(size_t)BQ * NQ * KS];
__device__ float g_ft[(size_t)BQ * NP * CF];   // (B, N, C)

typedef unsigned long long u64;

__device__ __forceinline__ u64 pack_key(float d, int idx) {
    return ((u64)__float_as_uint(d) << 32) | (unsigned int)idx;
}

// ---- packed f32x2 helpers (sm_103a) ----
__device__ __forceinline__ u64 f2_add(u64 a, u64 b) {
    u64 r; asm("add.rn.f32x2 %0, %1, %2;" : "=l"(r) : "l"(a), "l"(b)); return r;
}
__device__ __forceinline__ u64 f2_mul(u64 a, u64 b) {
    u64 r; asm("mul.rn.f32x2 %0, %1, %2;" : "=l"(r) : "l"(a), "l"(b)); return r;
}
__device__ __forceinline__ u64 f2_fma(u64 a, u64 b, u64 c) {
    u64 r; asm("fma.rn.f32x2 %0, %1, %2, %3;" : "=l"(r) : "l"(a), "l"(b), "l"(c)); return r;
}
__device__ __forceinline__ u64 f2_bcast(float x) {
    u64 r; asm("mov.b64 %0, {%1, %1};" : "=l"(r) : "f"(x)); return r;
}
__device__ __forceinline__ void f2_unpack(u64 v, float& lo, float& hi) {
    asm("mov.b64 {%0, %1}, %2;" : "=f"(lo), "=f"(hi) : "l"(v));
}

// Warp-wide bitonic sort, ascending, one key per lane.
__device__ __forceinline__ u64 warp_bitonic_sort(u64 key, int lane) {
#pragma unroll
    for (int k = 2; k <= 32; k <<= 1) {
#pragma unroll
        for (int j = k >> 1; j > 0; j >>= 1) {
            u64 other = __shfl_xor_sync(FULLM, key, j);
            bool take_min = (((lane & k) == 0) == ((lane & j) == 0));
            bool lt = key < other;
            key = (take_min == lt) ? key : other;
        }
    }
    return key;
}

// Keep lowest 32 of (top asc-sorted) U (cand asc-sorted), result asc-sorted.
__device__ __forceinline__ u64 warp_merge_topk(u64 top, u64 cand, int lane) {
    u64 crev = __shfl_sync(FULLM, cand, 31 - lane);
    u64 v = (top < crev) ? top : crev;   // bitonic sequence = lowest 32
#pragma unroll
    for (int j = 16; j > 0; j >>= 1) {   // bitonic cleanup
        u64 other = __shfl_xor_sync(FULLM, v, j);
        bool lower = (lane & j) == 0;
        bool lt = v < other;
        v = (lower == lt) ? v : other;
    }
    return v;
}

// ---------------------------------------------------------------------------
// Kernel 1: exact KNN, one WARP per query.
// Each lane handles 4 consecutive points per step via LDS.128 on SoA tiles
// (coords stored NEGATED); distances via packed f32x2 fma. Fast path is
// min-tree + 1 vote; survivors are compacted into a per-warp buffer and
// folded 32-at-a-time through bitonic sort + top-k merge.
// ---------------------------------------------------------------------------
__global__ __launch_bounds__(WPB * 32)
void knn_kernel(const float* __restrict__ xyz,
                const float* __restrict__ new_xyz) {
    const int b    = blockIdx.y;
    const int warp = threadIdx.x >> 5;
    const int lane = threadIdx.x & 31;
    const int q    = blockIdx.x * WPB + warp;
    const unsigned ltmask = (1u << lane) - 1u;

    const float* qp = new_xyz + ((size_t)b * NQ + q) * 3;
    const float qx = qp[0], qy = qp[1], qz = qp[2];
    const u64 qxx = f2_bcast(qx), qyy = f2_bcast(qy), qzz = f2_bcast(qz);

    __shared__ float s_x[TILE], s_y[TILE], s_z[TILE];  // 24 KB (negated)
    __shared__ u64   s_cand[WPB][CAP];                 // 10 KB

    u64 top = INFKEY;
    float thf = __int_as_float(0x7f800000);   // +inf
    int cnt = 0;

    for (int t0 = 0; t0 < NP; t0 += TILE) {
        __syncthreads();
        {
            const float* src = xyz + ((size_t)b * NP + t0) * 3;
#pragma unroll
            for (int k = 0; k < TILE / (WPB * 32); k++) {
                const int pt = threadIdx.x + k * (WPB * 32);
                s_x[pt] = -src[pt * 3];
                s_y[pt] = -src[pt * 3 + 1];
                s_z[pt] = -src[pt * 3 + 2];
            }
        }
        __syncthreads();

#pragma unroll 2
        for (int j = 0; j < TILE; j += 128) {
            const int o = j + 4 * lane;
            const ulonglong2 xs = *(const ulonglong2*)(s_x + o);
            const ulonglong2 ys = *(const ulonglong2*)(s_y + o);
            const ulonglong2 zs = *(const ulonglong2*)(s_z + o);

            const u64 dx01 = f2_add(qxx, xs.x), dx23 = f2_add(qxx, xs.y);
            const u64 dy01 = f2_add(qyy, ys.x), dy23 = f2_add(qyy, ys.y);
            const u64 dz01 = f2_add(qzz, zs.x), dz23 = f2_add(qzz, zs.y);

            u64 s01 = f2_mul(dz01, dz01);
            u64 s23 = f2_mul(dz23, dz23);
            s01 = f2_fma(dy01, dy01, s01);
            s23 = f2_fma(dy23, dy23, s23);
            s01 = f2_fma(dx01, dx01, s01);
            s23 = f2_fma(dx23, dx23, s23);

            float d0, d1, d2, d3;
            f2_unpack(s01, d0, d1);
            f2_unpack(s23, d2, d3);

            const float dmin = fminf(fminf(d0, d1), fminf(d2, d3));
            if (__any_sync(FULLM, dmin < thf)) {
                const bool p0 = d0 < thf, p1 = d1 < thf,
                           p2 = d2 < thf, p3 = d3 < thf;
                unsigned m;
                m = __ballot_sync(FULLM, p0);
                if (p0) s_cand[warp][cnt + __popc(m & ltmask)] =
                            pack_key(d0, t0 + o);
                cnt += __popc(m);
                m = __ballot_sync(FULLM, p1);
                if (p1) s_cand[warp][cnt + __popc(m & ltmask)] =
                            pack_key(d1, t0 + o + 1);
                cnt += __popc(m);
                m = __ballot_sync(FULLM, p2);
                if (p2) s_cand[warp][cnt + __popc(m & ltmask)] =
                            pack_key(d2, t0 + o + 2);
                cnt += __popc(m);
                m = __ballot_sync(FULLM, p3);
                if (p3) s_cand[warp][cnt + __popc(m & ltmask)] =
                            pack_key(d3, t0 + o + 3);
                cnt += __popc(m);

                __syncwarp(FULLM);
                while (cnt >= 32) {  // fold last 32 (order irrelevant: sorted)
                    u64 c = s_cand[warp][cnt - 32 + lane];
                    c   = warp_bitonic_sort(c, lane);
                    top = warp_merge_topk(top, c, lane);
                    cnt -= 32;
                    thf = __uint_as_float(
                        (unsigned)(__shfl_sync(FULLM, top, 31) >> 32));
                }
            }
        }
    }
    __syncwarp(FULLM);
    if (cnt > 0) {
        u64 c = (lane < cnt) ? s_cand[warp][lane] : INFKEY;
        c   = warp_bitonic_sort(c, lane);
        top = warp_merge_topk(top, c, lane);
    }

    // top is ascending by (dist, idx) -> slot order matches top_k output.
    g_idx[((size_t)b * NQ + q) * KS + lane] = (int)(top & 0xffffffffu);
}

// ---------------------------------------------------------------------------
// Kernel 0: feature transpose (B, C, N) -> (B, N, C).
// ---------------------------------------------------------------------------
__global__ __launch_bounds__(256)
void transpose_kernel(const float* __restrict__ feat) {
    __shared__ float t[32][33];
    const int b  = blockIdx.z;
    const int n0 = blockIdx.x * 32;
    const int c0 = blockIdx.y * 32;
    const int tx = threadIdx.x;
    const int ty = threadIdx.y;
#pragma unroll
    for (int i = 0; i < 4; i++) {
        const int c = c0 + ty + i * 8;
        t[ty + i * 8][tx] = feat[((size_t)b * CF + c) * NP + n0 + tx];
    }
    __syncthreads();
#pragma unroll
    for (int i = 0; i < 4; i++) {
        const int n = n0 + ty + i * 8;
        g_ft[((size_t)b * NP + n) * CF + c0 + tx] = t[tx][ty + i * 8];
    }
}

// ---------------------------------------------------------------------------
// Kernel 2: gather / center / transpose / concat. One query per block.
// ---------------------------------------------------------------------------
__global__ __launch_bounds__(128)
void group_kernel(const float* __restrict__ xyz,
                  const float* __restrict__ new_xyz,
                  float* __restrict__ out) {
    const int p   = blockIdx.x;
    const int b   = blockIdx.y;
    const int tid = threadIdx.x;
    const int w    = tid >> 5;
    const int lane = tid & 31;

    __shared__ int   sidx[KS];
    __shared__ float sfeat[KS][65];

    if (tid < KS) sidx[tid] = g_idx[((size_t)b * NQ + p) * KS + tid];
    __syncthreads();

    // Stage neighbor feature rows: warp w loads rows w, w+4, ... (256B each).
    for (int s = w; s < KS; s += 4) {
        const float2* row =
            (const float2*)(g_ft + ((size_t)b * NP + sidx[s]) * CF);
        const float2 v = row[lane];
        sfeat[s][lane * 2]     = v.x;
        sfeat[s][lane * 2 + 1] = v.y;
    }
    __syncthreads();

    const int i = sidx[lane];
    for (int c = w; c < OUTC; c += 4) {
        float v;
        if (c < 3) {
            v = xyz[((size_t)b * NP + i) * 3 + c] -
                new_xyz[((size_t)b * NQ + p) * 3 + c];
        } else {
            v = sfeat[lane][c - 3];
        }
        out[(((size_t)b * OUTC + c) * NQ + p) * KS + lane] = v;
    }
}

extern "C" void kernel_launch(void* const* d_in, const int* in_sizes, int n_in,
                              void* d_out, int out_size) {
    const float* xyz     = (const float*)d_in[0];  // (B, N, 3)
    const float* new_xyz = (const float*)d_in[1];  // (B, NPOINT, 3)
    const float* feat    = (const float*)d_in[2];  // (B, C, N)
    float* out = (float*)d_out;                    // (B, 67, NPOINT, 32)

    // knn first so ncu's (-s 5 -c 1) capture lands on it.
    dim3 g1(NQ / WPB, BQ);
    knn_kernel<<<g1, WPB * 32>>>(xyz, new_xyz);

    dim3 gt(NP / 32, CF / 32, BQ);
    transpose_kernel<<<gt, dim3(32, 8)>>>(feat);

    dim3 g2(NQ, BQ);
    group_kernel<<<g2, 128>>>(xyz, new_xyz, out);
}

// round 7
// speedup vs baseline: 1.5751x; 1.0156x over previous
#include <cuda_runtime.h>

// Problem constants
#define BQ 4          // batch
#define NP 16384      // points
#define NQ 4096       // queries (npoint)
#define CF 64         // feature channels
#define KS 32         // nsample
#define OUTC (CF + 3) // 67 output channels

#define WPB 8         // warps per block
#define QPW 2         // queries per warp
#define TILE 2048     // shared-memory tile of points
#define CAP 160       // per-(warp,query) candidate buffer

#define FULLM 0xffffffffu
// +inf distance, max index: any real key sorts below this.
#define INFKEY 0x7f800000ffffffffULL

// Scratch: final neighbor indices (2 MB) + transposed features (16 MB).
__device__ int   g_idx[(size_t)BQ * NQ * KS];
__device__ float g_ft[(size_t)BQ * NP * CF];   // (B, N, C)

typedef unsigned long long u64;

__device__ __forceinline__ u64 pack_key(float d, int idx) {
    return ((u64)__float_as_uint(d) << 32) | (unsigned int)idx;
}

// ---- packed f32x2 helpers (sm_103a) ----
__device__ __forceinline__ u64 f2_add(u64 a, u64 b) {
    u64 r; asm("add.rn.f32x2 %0, %1, %2;" : "=l"(r) : "l"(a), "l"(b)); return r;
}
__device__ __forceinline__ u64 f2_mul(u64 a, u64 b) {
    u64 r; asm("mul.rn.f32x2 %0, %1, %2;" : "=l"(r) : "l"(a), "l"(b)); return r;
}
__device__ __forceinline__ u64 f2_fma(u64 a, u64 b, u64 c) {
    u64 r; asm("fma.rn.f32x2 %0, %1, %2, %3;" : "=l"(r) : "l"(a), "l"(b), "l"(c)); return r;
}
__device__ __forceinline__ u64 f2_bcast(float x) {
    u64 r; asm("mov.b64 %0, {%1, %1};" : "=l"(r) : "f"(x)); return r;
}
__device__ __forceinline__ void f2_unpack(u64 v, float& lo, float& hi) {
    asm("mov.b64 {%0, %1}, %2;" : "=f"(lo), "=f"(hi) : "l"(v));
}

// Warp-wide bitonic sort, ascending, one key per lane.
__device__ __forceinline__ u64 warp_bitonic_sort(u64 key, int lane) {
#pragma unroll
    for (int k = 2; k <= 32; k <<= 1) {
#pragma unroll
        for (int j = k >> 1; j > 0; j >>= 1) {
            u64 other = __shfl_xor_sync(FULLM, key, j);
            bool take_min = (((lane & k) == 0) == ((lane & j) == 0));
            bool lt = key < other;
            key = (take_min == lt) ? key : other;
        }
    }
    return key;
}

// Keep lowest 32 of (top asc-sorted) U (cand asc-sorted), result asc-sorted.
__device__ __forceinline__ u64 warp_merge_topk(u64 top, u64 cand, int lane) {
    u64 crev = __shfl_sync(FULLM, cand, 31 - lane);
    u64 v = (top < crev) ? top : crev;   // bitonic sequence = lowest 32
#pragma unroll
    for (int j = 16; j > 0; j >>= 1) {   // bitonic cleanup
        u64 other = __shfl_xor_sync(FULLM, v, j);
        bool lower = (lane & j) == 0;
        bool lt = v < other;
        v = (lower == lt) ? v : other;
    }
    return v;
}

// Fold full 32-candidate batches from buf into (top, thf).
__device__ __forceinline__ void fold32(u64* buf, int& cnt, u64& top,
                                       float& thf, int lane) {
    while (cnt >= 32) {   // take LAST 32 (order irrelevant: batch gets sorted)
        u64 c = buf[cnt - 32 + lane];
        c   = warp_bitonic_sort(c, lane);
        top = warp_merge_topk(top, c, lane);
        cnt -= 32;
        thf = __uint_as_float((unsigned)(__shfl_sync(FULLM, top, 31) >> 32));
    }
}

// Compact passing lanes of one point-group into buf, 4 sub-ballots.
#define PUSH(buf, cnt, pred, dval, idxval)                                   \
    do {                                                                     \
        unsigned m_ = __ballot_sync(FULLM, pred);                            \
        if (pred) (buf)[(cnt) + __popc(m_ & ltmask)] = pack_key(dval, idxval); \
        (cnt) += __popc(m_);                                                 \
    } while (0)

// ---------------------------------------------------------------------------
// Kernel 1: exact KNN, one WARP per TWO queries.
// One tile read (3x LDS.128 / 128 pts) is amortized over 256 query-points,
// halving smem-crossbar traffic vs one-query-per-warp. Distances via packed
// f32x2 fma on negated SoA tiles. Exactness: strict 'd < thf' filter plus
// u64 (dist,idx) bitonic top-k preserves jax.lax.top_k's stable tie order.
// ---------------------------------------------------------------------------
__global__ __launch_bounds__(WPB * 32)
void knn_kernel(const float* __restrict__ xyz,
                const float* __restrict__ new_xyz) {
    const int b    = blockIdx.y;
    const int warp = threadIdx.x >> 5;
    const int lane = threadIdx.x & 31;
    const int q0   = (blockIdx.x * WPB + warp) * QPW;
    const unsigned ltmask = (1u << lane) - 1u;

    const float* qp = new_xyz + ((size_t)b * NQ + q0) * 3;
    const u64 qxx0 = f2_bcast(qp[0]), qyy0 = f2_bcast(qp[1]), qzz0 = f2_bcast(qp[2]);
    const u64 qxx1 = f2_bcast(qp[3]), qyy1 = f2_bcast(qp[4]), qzz1 = f2_bcast(qp[5]);

    __shared__ float s_x[TILE], s_y[TILE], s_z[TILE];  // 24 KB (negated)
    __shared__ u64   s_cand[WPB][QPW][CAP];            // 20 KB

    u64 top0 = INFKEY, top1 = INFKEY;
    float thf0 = __int_as_float(0x7f800000);
    float thf1 = __int_as_float(0x7f800000);
    int cnt0 = 0, cnt1 = 0;

    for (int t0 = 0; t0 < NP; t0 += TILE) {
        __syncthreads();
        {
            const float* src = xyz + ((size_t)b * NP + t0) * 3;
#pragma unroll
            for (int k = 0; k < TILE / (WPB * 32); k++) {
                const int pt = threadIdx.x + k * (WPB * 32);
                s_x[pt] = -src[pt * 3];
                s_y[pt] = -src[pt * 3 + 1];
                s_z[pt] = -src[pt * 3 + 2];
            }
        }
        __syncthreads();

#pragma unroll 2
        for (int j = 0; j < TILE; j += 128) {
            const int o = j + 4 * lane;
            const ulonglong2 xs = *(const ulonglong2*)(s_x + o);
            const ulonglong2 ys = *(const ulonglong2*)(s_y + o);
            const ulonglong2 zs = *(const ulonglong2*)(s_z + o);

            // query 0 distances
            u64 a01, a23;
            {
                const u64 dx01 = f2_add(qxx0, xs.x), dx23 = f2_add(qxx0, xs.y);
                const u64 dy01 = f2_add(qyy0, ys.x), dy23 = f2_add(qyy0, ys.y);
                const u64 dz01 = f2_add(qzz0, zs.x), dz23 = f2_add(qzz0, zs.y);
                a01 = f2_mul(dz01, dz01);
                a23 = f2_mul(dz23, dz23);
                a01 = f2_fma(dy01, dy01, a01);
                a23 = f2_fma(dy23, dy23, a23);
                a01 = f2_fma(dx01, dx01, a01);
                a23 = f2_fma(dx23, dx23, a23);
            }
            // query 1 distances
            u64 b01, b23;
            {
                const u64 dx01 = f2_add(qxx1, xs.x), dx23 = f2_add(qxx1, xs.y);
                const u64 dy01 = f2_add(qyy1, ys.x), dy23 = f2_add(qyy1, ys.y);
                const u64 dz01 = f2_add(qzz1, zs.x), dz23 = f2_add(qzz1, zs.y);
                b01 = f2_mul(dz01, dz01);
                b23 = f2_mul(dz23, dz23);
                b01 = f2_fma(dy01, dy01, b01);
                b23 = f2_fma(dy23, dy23, b23);
                b01 = f2_fma(dx01, dx01, b01);
                b23 = f2_fma(dx23, dx23, b23);
            }

            float d0, d1, d2, d3, e0, e1, e2, e3;
            f2_unpack(a01, d0, d1);  f2_unpack(a23, d2, d3);
            f2_unpack(b01, e0, e1);  f2_unpack(b23, e2, e3);

            const bool hit0 = fminf(fminf(d0, d1), fminf(d2, d3)) < thf0;
            const bool hit1 = fminf(fminf(e0, e1), fminf(e2, e3)) < thf1;
            if (__any_sync(FULLM, hit0 | hit1)) {
                const int gi = t0 + o;
                PUSH(s_cand[warp][0], cnt0, d0 < thf0, d0, gi);
                PUSH(s_cand[warp][0], cnt0, d1 < thf0, d1, gi + 1);
                PUSH(s_cand[warp][0], cnt0, d2 < thf0, d2, gi + 2);
                PUSH(s_cand[warp][0], cnt0, d3 < thf0, d3, gi + 3);
                PUSH(s_cand[warp][1], cnt1, e0 < thf1, e0, gi);
                PUSH(s_cand[warp][1], cnt1, e1 < thf1, e1, gi + 1);
                PUSH(s_cand[warp][1], cnt1, e2 < thf1, e2, gi + 2);
                PUSH(s_cand[warp][1], cnt1, e3 < thf1, e3, gi + 3);
                __syncwarp(FULLM);
                fold32(s_cand[warp][0], cnt0, top0, thf0, lane);
                fold32(s_cand[warp][1], cnt1, top1, thf1, lane);
            }
        }
    }
    __syncwarp(FULLM);
    if (cnt0 > 0) {
        u64 c = (lane < cnt0) ? s_cand[warp][0][lane] : INFKEY;
        c = warp_bitonic_sort(c, lane);
        top0 = warp_merge_topk(top0, c, lane);
    }
    if (cnt1 > 0) {
        u64 c = (lane < cnt1) ? s_cand[warp][1][lane] : INFKEY;
        c = warp_bitonic_sort(c, lane);
        top1 = warp_merge_topk(top1, c, lane);
    }

    // tops are ascending by (dist, idx) -> slot order matches top_k output.
    g_idx[((size_t)b * NQ + q0) * KS + lane]      = (int)(top0 & 0xffffffffu);
    g_idx[((size_t)b * NQ + q0 + 1) * KS + lane]  = (int)(top1 & 0xffffffffu);
}

// ---------------------------------------------------------------------------
// Kernel 0: feature transpose (B, C, N) -> (B, N, C).
// ---------------------------------------------------------------------------
__global__ __launch_bounds__(256)
void transpose_kernel(const float* __restrict__ feat) {
    __shared__ float t[32][33];
    const int b  = blockIdx.z;
    const int n0 = blockIdx.x * 32;
    const int c0 = blockIdx.y * 32;
    const int tx = threadIdx.x;
    const int ty = threadIdx.y;
#pragma unroll
    for (int i = 0; i < 4; i++) {
        const int c = c0 + ty + i * 8;
        t[ty + i * 8][tx] = feat[((size_t)b * CF + c) * NP + n0 + tx];
    }
    __syncthreads();
#pragma unroll
    for (int i = 0; i < 4; i++) {
        const int n = n0 + ty + i * 8;
        g_ft[((size_t)b * NP + n) * CF + c0 + tx] = t[tx][ty + i * 8];
    }
}

// ---------------------------------------------------------------------------
// Kernel 2: gather / center / transpose / concat. One query per block.
// ---------------------------------------------------------------------------
__global__ __launch_bounds__(128)
void group_kernel(const float* __restrict__ xyz,
                  const float* __restrict__ new_xyz,
                  float* __restrict__ out) {
    const int p   = blockIdx.x;
    const int b   = blockIdx.y;
    const int tid = threadIdx.x;
    const int w    = tid >> 5;
    const int lane = tid & 31;

    __shared__ int   sidx[KS];
    __shared__ float sfeat[KS][65];

    if (tid < KS) sidx[tid] = g_idx[((size_t)b * NQ + p) * KS + tid];
    __syncthreads();

    // Stage neighbor feature rows: warp w loads rows w, w+4, ... (256B each).
    for (int s = w; s < KS; s += 4) {
        const float2* row =
            (const float2*)(g_ft + ((size_t)b * NP + sidx[s]) * CF);
        const float2 v = row[lane];
        sfeat[s][lane * 2]     = v.x;
        sfeat[s][lane * 2 + 1] = v.y;
    }
    __syncthreads();

    const int i = sidx[lane];
    for (int c = w; c < OUTC; c += 4) {
        float v;
        if (c < 3) {
            v = xyz[((size_t)b * NP + i) * 3 + c] -
                new_xyz[((size_t)b * NQ + p) * 3 + c];
        } else {
            v = sfeat[lane][c - 3];
        }
        out[(((size_t)b * OUTC + c) * NQ + p) * KS + lane] = v;
    }
}

extern "C" void kernel_launch(void* const* d_in, const int* in_sizes, int n_in,
                              void* d_out, int out_size) {
    const float* xyz     = (const float*)d_in[0];  // (B, N, 3)
    const float* new_xyz = (const float*)d_in[1];  // (B, NPOINT, 3)
    const float* feat    = (const float*)d_in[2];  // (B, C, N)
    float* out = (float*)d_out;                    // (B, 67, NPOINT, 32)

    // knn first so ncu's (-s 5 -c 1) capture lands on it.
    dim3 g1(NQ / (WPB * QPW), BQ);
    knn_kernel<<<g1, WPB * 32>>>(xyz, new_xyz);

    dim3 gt(NP / 32, CF / 32, BQ);
    transpose_kernel<<<gt, dim3(32, 8)>>>(feat);

    dim3 g2(NQ, BQ);
    group_kernel<<<g2, 128>>>(xyz, new_xyz, out);
}